// round 15
// baseline (speedup 1.0000x reference)
#include <cuda_runtime.h>
#include <cstdint>
#include <cstddef>
#include <vector>
#include <algorithm>

#define DIMS 256
#define N_ITERS 100
#define RPB 96            // rows per tile
#define TPB 192
#define NB 148            // persistent blocks = SMs
#define PITCH4 65         // float4 per row (padded), conflict-free both phases
#define TILE4 (RPB * PITCH4)

// ---------------- device state ----------------
__device__ __align__(16) float g_c[2][DIMS];
__device__ float  g_q[2];
__device__ double g_sum1[DIMS];
__device__ double g_tot[DIMS];
__device__ unsigned long long g_cnt1;
__device__ unsigned g_arrive;
__device__ float  g_xsq[262144];

// ---------------- x_sq: XLA row-reduce, float2 pattern (bit-exact, DO NOT TOUCH) ----
__global__ void xsq_kernel(const float* __restrict__ x, int n) {
    int row  = blockIdx.x * (blockDim.x >> 5) + (threadIdx.x >> 5);
    int lane = threadIdx.x & 31;
    if (row >= n) return;
    const float2* xr = (const float2*)(x + (size_t)row * DIMS);
    float acc = 0.f;
    #pragma unroll
    for (int j = 0; j < 4; j++) {
        float2 v = xr[lane + 32 * j];
        acc = __fadd_rn(acc, __fmul_rn(v.x, v.x));
        acc = __fadd_rn(acc, __fmul_rn(v.y, v.y));
    }
    #pragma unroll
    for (int o = 16; o > 0; o >>= 1)
        acc = __fadd_rn(acc, __shfl_xor_sync(0xffffffffu, acc, o));
    if (lane == 0) g_xsq[row] = acc;
}

__device__ __forceinline__ void q_from_centers(int d) {
    if (d < 64) {
        int w = d >> 5, lane = d & 31;
        const float2* cr = (const float2*)g_c[w];
        float acc = 0.f;
        #pragma unroll
        for (int j = 0; j < 4; j++) {
            float2 v = cr[lane + 32 * j];
            acc = __fadd_rn(acc, __fmul_rn(v.x, v.x));
            acc = __fadd_rn(acc, __fmul_rn(v.y, v.y));
        }
        #pragma unroll
        for (int o = 16; o > 0; o >>= 1)
            acc = __fadd_rn(acc, __shfl_xor_sync(0xffffffffu, acc, o));
        if (lane == 0) g_q[w] = acc;
    }
}

__global__ void init_kernel(const float* __restrict__ x, int i0, int i1) {
    int d = threadIdx.x;
    g_c[0][d] = x[(size_t)i0 * DIMS + d];
    g_c[1][d] = x[(size_t)i1 * DIMS + d];
    g_sum1[d] = 0.0;
    g_tot[d]  = 0.0;
    if (d == 0) { g_cnt1 = 0ull; g_arrive = 0u; }
    __syncthreads();
    q_from_centers(d);
}

// per-column double totals (once per launch; order-free)
__global__ void tot_kernel(const float* __restrict__ x, int n) {
    int c = threadIdx.x;
    double acc = 0.0;
    for (int r = blockIdx.x; r < n; r += gridDim.x)
        acc += (double)x[(size_t)r * DIMS + c];
    atomicAdd(&g_tot[c], acc);
}

// ---------------- persistent double-buffered assign + fused update ----------------
extern __shared__ float4 s4[];   // 2 * TILE4
__global__ __launch_bounds__(TPB, 1) void assign_kernel(const float* __restrict__ x,
                                                        int n, int do_update) {
    __shared__ float4 c04[64], c14[64];
    __shared__ double sdbl[2][64][4];     // thirds 1,2 partials
    __shared__ unsigned sm_m1[3];
    __shared__ int slast;

    float4* bufs = s4;
    const int tid = threadIdx.x, lane = tid & 31, w = tid >> 5;
    const int c4 = tid & 63, third = tid >> 6;      // sum/load-phase role

    for (int i = tid; i < 64; i += TPB) {
        c04[i] = ((const float4*)g_c[0])[i];
        c14[i] = ((const float4*)g_c[1])[i];
    }
    const float q0 = g_q[0], q1 = g_q[1];
    const int ngroups = (n + RPB - 1) / RPB;

    uint32_t sbase = (uint32_t)__cvta_generic_to_shared(bufs)
                   + 16u * (unsigned)(third * PITCH4 + c4);   // per-thread dst base

    double aX = 0, aY = 0, aZ = 0, aW = 0;
    unsigned long long myCnt = 0;

    // strided load: e = tid + 192k => row = third + 3k, col4 = c4 (constants!)
    auto issue_tile = [&](int g, int b) {
        int base  = g * RPB;
        int valid = min(RPB, n - base);
        const float4* src = (const float4*)x + (size_t)base * 64 + tid;
        uint32_t dst = sbase + (unsigned)(b * TILE4) * 16u;
        if (valid == RPB) {               // full tile: no bounds checks
            #pragma unroll
            for (int k = 0; k < 32; k++)
                asm volatile("cp.async.cg.shared.global [%0], [%1], 16;"
                             :: "r"(dst + k * (3 * PITCH4 * 16)),
                                "l"(src + k * (3 * 64)) : "memory");
        } else {
            int tot4 = valid * 64;
            #pragma unroll
            for (int k = 0; k < 32; k++) {
                if (tid + k * TPB < tot4)
                    asm volatile("cp.async.cg.shared.global [%0], [%1], 16;"
                                 :: "r"(dst + k * (3 * PITCH4 * 16)),
                                    "l"(src + k * (3 * 64)) : "memory");
            }
        }
        asm volatile("cp.async.commit_group;" ::: "memory");
    };

    int g = blockIdx.x;
    issue_tile(g, 0);
    int cur = 0;

    for (; g < ngroups; g += NB) {
        int gn = g + NB;
        if (gn < ngroups) {
            issue_tile(gn, cur ^ 1);
            asm volatile("cp.async.wait_group 1;" ::: "memory");
        } else {
            asm volatile("cp.async.wait_group 0;" ::: "memory");
        }
        __syncthreads();

        const int base  = g * RPB;
        const int valid = min(RPB, n - base);

        // ---- dot: threads 0-95, thread-per-row, bit-exact serial ascending-k FMA ----
        if (tid < RPB) {
            float xsq = (tid < valid) ? __ldg(&g_xsq[base + tid]) : 0.f;
            const float4* row = bufs + cur * TILE4 + min(tid, valid - 1) * PITCH4;
            float s0 = 0.f, s1 = 0.f;
            #pragma unroll 16
            for (int j = 0; j < 64; j++) {
                float4 v  = row[j];
                float4 c0 = c04[j];
                float4 c1 = c14[j];
                s0 = __fmaf_rn(v.x, c0.x, s0); s1 = __fmaf_rn(v.x, c1.x, s1);
                s0 = __fmaf_rn(v.y, c0.y, s0); s1 = __fmaf_rn(v.y, c1.y, s1);
                s0 = __fmaf_rn(v.z, c0.z, s0); s1 = __fmaf_rn(v.z, c1.z, s1);
                s0 = __fmaf_rn(v.w, c0.w, s0); s1 = __fmaf_rn(v.w, c1.w, s1);
            }
            float d20 = __fadd_rn(__fsub_rn(xsq, __fmul_rn(2.0f, s0)), q0);
            float d21 = __fadd_rn(__fsub_rn(xsq, __fmul_rn(2.0f, s1)), q1);
            bool a1 = (tid < valid) && (d21 < d20);     // argmin, tie -> cluster 0
            unsigned m1 = __ballot_sync(0xffffffffu, a1);
            if (lane == 0) { sm_m1[w] = m1; myCnt += (unsigned)__popc(m1); }
        }
        __syncthreads();

        // ---- cluster-1 sums: (col-group c4, third) x 32 rows, warp-uniform popping ----
        {
            unsigned m = sm_m1[third];
            const float4* colp = bufs + cur * TILE4 + third * 32 * PITCH4 + c4;
            float pX = 0.f, pY = 0.f, pZ = 0.f, pW = 0.f;
            while (m) {
                int r = __ffs(m) - 1; m &= m - 1;
                float4 v = colp[r * PITCH4];
                pX += v.x; pY += v.y; pZ += v.z; pW += v.w;
            }
            aX += (double)pX; aY += (double)pY; aZ += (double)pZ; aW += (double)pW;
        }
        __syncthreads();        // tile consumed before next overwrite
        cur ^= 1;
    }

    // ---- combine thirds, one atomicAdd set per block ----
    if (third > 0) {
        sdbl[third - 1][c4][0] = aX; sdbl[third - 1][c4][1] = aY;
        sdbl[third - 1][c4][2] = aZ; sdbl[third - 1][c4][3] = aW;
    }
    __syncthreads();
    if (third == 0) {
        atomicAdd(&g_sum1[4 * c4 + 0], aX + sdbl[0][c4][0] + sdbl[1][c4][0]);
        atomicAdd(&g_sum1[4 * c4 + 1], aY + sdbl[0][c4][1] + sdbl[1][c4][1]);
        atomicAdd(&g_sum1[4 * c4 + 2], aZ + sdbl[0][c4][2] + sdbl[1][c4][2]);
        atomicAdd(&g_sum1[4 * c4 + 3], aW + sdbl[0][c4][3] + sdbl[1][c4][3]);
    }
    if (tid < RPB && lane == 0) atomicAdd(&g_cnt1, myCnt);

    // ---- last-arriving block performs the center update inline ----
    __threadfence();
    __syncthreads();
    if (tid == 0) slast = (atomicAdd(&g_arrive, 1u) == NB - 1) ? 1 : 0;
    __syncthreads();
    if (!slast) return;

    if (do_update) {
        __threadfence();                              // acquire all blocks' atomics
        unsigned long long c1n = *(volatile unsigned long long*)&g_cnt1;
        float cnt1f = (float)c1n;                     // exact (<2^24)
        float cnt0f = (float)(long long)((long long)n - (long long)c1n);
        for (int d = tid; d < DIMS; d += TPB) {
            double s1d = g_sum1[d];
            float  s1  = (float)s1d;
            float  s0  = (float)(g_tot[d] - s1d);
            float c0 = (cnt0f > 0.f) ? __fdiv_rn(s0, fmaxf(cnt0f, 1.f)) : g_c[0][d];
            float c1 = (cnt1f > 0.f) ? __fdiv_rn(s1, fmaxf(cnt1f, 1.f)) : g_c[1][d];
            g_c[0][d] = c0; g_c[1][d] = c1;
            g_sum1[d] = 0.0;
        }
        __syncthreads();
        q_from_centers(tid);
        if (tid == 0) g_cnt1 = 0ull;
    }
    if (tid == 0) g_arrive = 0u;
}

__global__ void output_kernel(float* __restrict__ out, int n) {
    int d = threadIdx.x;
    unsigned long long c1n = g_cnt1;
    float mean = __fdiv_rn((float)c1n, (float)n);
    int maj = (mean > 0.5f) ? 1 : 0;
    float cm  = maj ? (float)c1n : (float)(long long)((long long)n - (long long)c1n);
    float cnt = fmaxf(cm, 1.0f);
    double s  = maj ? g_sum1[d] : (g_tot[d] - g_sum1[d]);
    out[d] = __fdiv_rn((float)s, cnt);
}

// ---------------- host: JAX threefry (partitionable/foldlike) init ----------------
static inline uint32_t rotl32(uint32_t v, int r) { return (v << r) | (v >> (32 - r)); }

static void tf2x32(uint32_t k0, uint32_t k1, uint32_t x0, uint32_t x1,
                   uint32_t* o0, uint32_t* o1) {
    uint32_t ks2 = k0 ^ k1 ^ 0x1BD11BDAu;
    x0 += k0; x1 += k1;
    static const int R0[4] = {13, 15, 26, 6};
    static const int R1[4] = {17, 29, 16, 24};
#define TF_RND(r) { x0 += x1; x1 = rotl32(x1, (r)); x1 ^= x0; }
    for (int i = 0; i < 4; i++) TF_RND(R0[i]);  x0 += k1;  x1 += ks2 + 1u;
    for (int i = 0; i < 4; i++) TF_RND(R1[i]);  x0 += ks2; x1 += k0 + 2u;
    for (int i = 0; i < 4; i++) TF_RND(R0[i]);  x0 += k0;  x1 += k1 + 3u;
    for (int i = 0; i < 4; i++) TF_RND(R1[i]);  x0 += k1;  x1 += ks2 + 4u;
    for (int i = 0; i < 4; i++) TF_RND(R0[i]);  x0 += ks2; x1 += k0 + 5u;
#undef TF_RND
    *o0 = x0; *o1 = x1;
}

static void init_indices(int n, int* pi0, int* pi1) {
    uint32_t K0, K1, S0, S1, T0, T1;
    tf2x32(0u, 42u, 0u, 0u, &K0, &K1);
    tf2x32(0u, 42u, 0u, 1u, &S0, &S1);
    tf2x32(K0, K1, 0u, 1u, &T0, &T1);

    std::vector<uint32_t> k1v((size_t)n), k2v((size_t)n);
    for (int i = 0; i < n; i++) {
        uint32_t a, b;
        tf2x32(S0, S1, 0u, (uint32_t)i, &a, &b); k1v[i] = a ^ b;
        tf2x32(T0, T1, 0u, (uint32_t)i, &a, &b); k2v[i] = a ^ b;
    }
    long q0 = -1, q1 = -1;
    for (int p = 0; p < n; p++) {
        uint32_t v = k2v[p];
        if (q0 < 0 || v < k2v[q0]) { q1 = q0; q0 = p; }
        else if (q1 < 0 || v < k2v[q1]) { q1 = p; }
    }
    std::vector<int> idx((size_t)n);
    for (int i = 0; i < n; i++) idx[i] = i;
    std::stable_sort(idx.begin(), idx.end(),
                     [&](int a, int b) { return k1v[a] < k1v[b]; });
    *pi0 = idx[q0];
    *pi1 = idx[q1];
}

// ---------------- entry ----------------
extern "C" void kernel_launch(void* const* d_in, const int* in_sizes, int n_in,
                              void* d_out, int out_size) {
    const float* x = (const float*)d_in[0];
    const int n = in_sizes[0] / DIMS;

    int i0 = 0, i1 = 1;
    init_indices(n, &i0, &i1);

    const int smem_bytes = 2 * TILE4 * 16;    // 199,680 B dynamic
    static bool attr_set = false;
    if (!attr_set) {
        cudaFuncSetAttribute(assign_kernel,
                             cudaFuncAttributeMaxDynamicSharedMemorySize, smem_bytes);
        attr_set = true;
    }

    init_kernel<<<1, DIMS>>>(x, i0, i1);
    xsq_kernel<<<(n + 7) / 8, 256>>>(x, n);
    tot_kernel<<<592, DIMS>>>(x, n);
    for (int t = 0; t < N_ITERS; t++)
        assign_kernel<<<NB, TPB, smem_bytes>>>(x, n, (t < N_ITERS - 1) ? 1 : 0);
    output_kernel<<<1, DIMS>>>((float*)d_out, n);
}

// round 17
// speedup vs baseline: 1.0518x; 1.0518x over previous
#include <cuda_runtime.h>
#include <cstdint>
#include <cstddef>
#include <vector>
#include <algorithm>

#define DIMS 256
#define N_ITERS 100
#define RPB 32            // rows per tile (n = 6250 * 32 exactly)
#define TPB 64
#define BPSM 3
#define NB (148 * BPSM)   // persistent blocks, 3 per SM
#define PITCH4 65         // float4 per row (padded), conflict-free both phases
#define TILE4 (RPB * PITCH4)   // 2080 float4 = 33,280 B; x2 buffers = 66,560 B

// ---------------- device state ----------------
__device__ __align__(16) float g_c[2][DIMS];
__device__ float  g_q[2];
__device__ double g_sum1[DIMS];
__device__ double g_tot[DIMS];
__device__ unsigned long long g_cnt1;
__device__ unsigned g_arrive;
__device__ float  g_xsq[262144];

// ---------------- x_sq: XLA row-reduce, float2 pattern (bit-exact, DO NOT TOUCH) ----
__global__ void xsq_kernel(const float* __restrict__ x, int n) {
    int row  = blockIdx.x * (blockDim.x >> 5) + (threadIdx.x >> 5);
    int lane = threadIdx.x & 31;
    if (row >= n) return;
    const float2* xr = (const float2*)(x + (size_t)row * DIMS);
    float acc = 0.f;
    #pragma unroll
    for (int j = 0; j < 4; j++) {
        float2 v = xr[lane + 32 * j];
        acc = __fadd_rn(acc, __fmul_rn(v.x, v.x));
        acc = __fadd_rn(acc, __fmul_rn(v.y, v.y));
    }
    #pragma unroll
    for (int o = 16; o > 0; o >>= 1)
        acc = __fadd_rn(acc, __shfl_xor_sync(0xffffffffu, acc, o));
    if (lane == 0) g_xsq[row] = acc;
}

__device__ __forceinline__ void q_from_centers(int d) {
    if (d < 64) {
        int w = d >> 5, lane = d & 31;
        const float2* cr = (const float2*)g_c[w];
        float acc = 0.f;
        #pragma unroll
        for (int j = 0; j < 4; j++) {
            float2 v = cr[lane + 32 * j];
            acc = __fadd_rn(acc, __fmul_rn(v.x, v.x));
            acc = __fadd_rn(acc, __fmul_rn(v.y, v.y));
        }
        #pragma unroll
        for (int o = 16; o > 0; o >>= 1)
            acc = __fadd_rn(acc, __shfl_xor_sync(0xffffffffu, acc, o));
        if (lane == 0) g_q[w] = acc;
    }
}

__global__ void init_kernel(const float* __restrict__ x, int i0, int i1) {
    int d = threadIdx.x;
    g_c[0][d] = x[(size_t)i0 * DIMS + d];
    g_c[1][d] = x[(size_t)i1 * DIMS + d];
    g_sum1[d] = 0.0;
    g_tot[d]  = 0.0;
    if (d == 0) { g_cnt1 = 0ull; g_arrive = 0u; }
    __syncthreads();
    q_from_centers(d);
}

// per-column double totals (once per launch; order-free)
__global__ void tot_kernel(const float* __restrict__ x, int n) {
    int c = threadIdx.x;
    double acc = 0.0;
    for (int r = blockIdx.x; r < n; r += gridDim.x)
        acc += (double)x[(size_t)r * DIMS + c];
    atomicAdd(&g_tot[c], acc);
}

// ---------------- persistent double-buffered assign, 3 blocks/SM ----------------
extern __shared__ float4 s4[];   // 2 * TILE4
__global__ __launch_bounds__(TPB, BPSM) void assign_kernel(const float* __restrict__ x,
                                                           int n, int do_update) {
    __shared__ float4 c04[64], c14[64];
    __shared__ unsigned sm_m1;
    __shared__ int slast;

    float4* bufs = s4;
    const int tid = threadIdx.x, lane = tid & 31;

    if (tid < 64) c04[tid] = ((const float4*)g_c[0])[tid];
    else          ;
    { int t2 = tid; c14[t2] = ((const float4*)g_c[1])[t2]; }   // tid 0..63 covers all 64
    const float q0 = g_q[0], q1 = g_q[1];
    const int ngroups = (n + RPB - 1) / RPB;      // 6250 (exact)

    // load mapping: e = tid + 64k -> row=k, col4=tid (compile-time strides)
    uint32_t sbase = (uint32_t)__cvta_generic_to_shared(bufs) + 16u * (unsigned)tid;

    double aX = 0, aY = 0, aZ = 0, aW = 0;
    unsigned long long myCnt = 0;

    auto issue_tile = [&](int g, int b) {
        const float4* src = (const float4*)x + (size_t)g * (RPB * 64) + tid;
        uint32_t dst = sbase + (unsigned)(b * TILE4) * 16u;
        int valid = min(RPB, n - g * RPB);
        if (valid == RPB) {                  // always true for n % 32 == 0
            #pragma unroll
            for (int k = 0; k < RPB; k++)
                asm volatile("cp.async.cg.shared.global [%0], [%1], 16;"
                             :: "r"(dst + k * (PITCH4 * 16)),
                                "l"(src + k * 64) : "memory");
        } else {
            for (int k = 0; k < RPB; k++) {
                float4 z = {0.f, 0.f, 0.f, 0.f};
                if (k < valid)
                    asm volatile("cp.async.cg.shared.global [%0], [%1], 16;"
                                 :: "r"(dst + k * (PITCH4 * 16)),
                                    "l"(src + k * 64) : "memory");
                else
                    bufs[b * TILE4 + k * PITCH4 + tid] = z;
            }
        }
        asm volatile("cp.async.commit_group;" ::: "memory");
    };

    int g = blockIdx.x;
    if (g < ngroups) issue_tile(g, 0);
    asm volatile("cp.async.commit_group;" ::: "memory");   // keep group count aligned
    int cur = 0;

    for (; g < ngroups; g += NB) {
        int gn = g + NB;
        if (gn < ngroups) {
            issue_tile(gn, cur ^ 1);
            asm volatile("cp.async.wait_group 1;" ::: "memory");
        } else {
            asm volatile("cp.async.wait_group 0;" ::: "memory");
        }
        __syncthreads();

        const int base  = g * RPB;
        const int valid = min(RPB, n - base);

        // ---- dot: warp 0, thread-per-row, bit-exact serial ascending-k FMA ----
        if (tid < 32) {
            float xsq = (tid < valid) ? __ldg(&g_xsq[base + tid]) : 0.f;
            const float4* row = bufs + cur * TILE4 + tid * PITCH4;
            float s0 = 0.f, s1 = 0.f;
            #pragma unroll 16
            for (int j = 0; j < 64; j++) {
                float4 v  = row[j];
                float4 c0 = c04[j];
                float4 c1 = c14[j];
                s0 = __fmaf_rn(v.x, c0.x, s0); s1 = __fmaf_rn(v.x, c1.x, s1);
                s0 = __fmaf_rn(v.y, c0.y, s0); s1 = __fmaf_rn(v.y, c1.y, s1);
                s0 = __fmaf_rn(v.z, c0.z, s0); s1 = __fmaf_rn(v.z, c1.z, s1);
                s0 = __fmaf_rn(v.w, c0.w, s0); s1 = __fmaf_rn(v.w, c1.w, s1);
            }
            float d20 = __fadd_rn(__fsub_rn(xsq, __fmul_rn(2.0f, s0)), q0);
            float d21 = __fadd_rn(__fsub_rn(xsq, __fmul_rn(2.0f, s1)), q1);
            bool a1 = (tid < valid) && (d21 < d20);     // argmin, tie -> cluster 0
            unsigned m1 = __ballot_sync(0xffffffffu, a1);
            if (lane == 0) { sm_m1 = m1; myCnt += (unsigned)__popc(m1); }
        }
        __syncthreads();

        // ---- cluster-1 sums: 64 threads, col-group tid x 32 rows, select-FMA ----
        {
            unsigned m = sm_m1;
            const float4* colp = bufs + cur * TILE4 + tid;
            float pX = 0.f, pY = 0.f, pZ = 0.f, pW = 0.f;
            #pragma unroll
            for (int r = 0; r < RPB; r++) {
                float ww = ((m >> r) & 1u) ? 1.0f : 0.0f;   // exact weight
                float4 v = colp[r * PITCH4];
                pX = __fmaf_rn(v.x, ww, pX);
                pY = __fmaf_rn(v.y, ww, pY);
                pZ = __fmaf_rn(v.z, ww, pZ);
                pW = __fmaf_rn(v.w, ww, pW);
            }
            aX += (double)pX; aY += (double)pY; aZ += (double)pZ; aW += (double)pW;
        }
        __syncthreads();        // tile consumed before next overwrite
        cur ^= 1;
    }

    // ---- one atomicAdd set per block ----
    atomicAdd(&g_sum1[4 * tid + 0], aX);
    atomicAdd(&g_sum1[4 * tid + 1], aY);
    atomicAdd(&g_sum1[4 * tid + 2], aZ);
    atomicAdd(&g_sum1[4 * tid + 3], aW);
    if (tid == 0) atomicAdd(&g_cnt1, myCnt);

    // ---- last-arriving block performs the center update inline ----
    __threadfence();
    __syncthreads();
    if (tid == 0) slast = (atomicAdd(&g_arrive, 1u) == NB - 1) ? 1 : 0;
    __syncthreads();
    if (!slast) return;

    if (do_update) {
        __threadfence();                              // acquire all blocks' atomics
        unsigned long long c1n = *(volatile unsigned long long*)&g_cnt1;
        float cnt1f = (float)c1n;                     // exact (<2^24)
        float cnt0f = (float)(long long)((long long)n - (long long)c1n);
        for (int d = tid; d < DIMS; d += TPB) {
            double s1d = g_sum1[d];
            float  s1  = (float)s1d;
            float  s0  = (float)(g_tot[d] - s1d);
            float c0 = (cnt0f > 0.f) ? __fdiv_rn(s0, fmaxf(cnt0f, 1.f)) : g_c[0][d];
            float c1 = (cnt1f > 0.f) ? __fdiv_rn(s1, fmaxf(cnt1f, 1.f)) : g_c[1][d];
            g_c[0][d] = c0; g_c[1][d] = c1;
            g_sum1[d] = 0.0;
        }
        __syncthreads();
        q_from_centers(tid);
        if (tid == 0) g_cnt1 = 0ull;
    }
    if (tid == 0) g_arrive = 0u;
}

__global__ void output_kernel(float* __restrict__ out, int n) {
    int d = threadIdx.x;
    unsigned long long c1n = g_cnt1;
    float mean = __fdiv_rn((float)c1n, (float)n);
    int maj = (mean > 0.5f) ? 1 : 0;
    float cm  = maj ? (float)c1n : (float)(long long)((long long)n - (long long)c1n);
    float cnt = fmaxf(cm, 1.0f);
    double s  = maj ? g_sum1[d] : (g_tot[d] - g_sum1[d]);
    out[d] = __fdiv_rn((float)s, cnt);
}

// ---------------- host: JAX threefry (partitionable/foldlike) init ----------------
static inline uint32_t rotl32(uint32_t v, int r) { return (v << r) | (v >> (32 - r)); }

static void tf2x32(uint32_t k0, uint32_t k1, uint32_t x0, uint32_t x1,
                   uint32_t* o0, uint32_t* o1) {
    uint32_t ks2 = k0 ^ k1 ^ 0x1BD11BDAu;
    x0 += k0; x1 += k1;
    static const int R0[4] = {13, 15, 26, 6};
    static const int R1[4] = {17, 29, 16, 24};
#define TF_RND(r) { x0 += x1; x1 = rotl32(x1, (r)); x1 ^= x0; }
    for (int i = 0; i < 4; i++) TF_RND(R0[i]);  x0 += k1;  x1 += ks2 + 1u;
    for (int i = 0; i < 4; i++) TF_RND(R1[i]);  x0 += ks2; x1 += k0 + 2u;
    for (int i = 0; i < 4; i++) TF_RND(R0[i]);  x0 += k0;  x1 += k1 + 3u;
    for (int i = 0; i < 4; i++) TF_RND(R1[i]);  x0 += k1;  x1 += ks2 + 4u;
    for (int i = 0; i < 4; i++) TF_RND(R0[i]);  x0 += ks2; x1 += k0 + 5u;
#undef TF_RND
    *o0 = x0; *o1 = x1;
}

static void init_indices(int n, int* pi0, int* pi1) {
    uint32_t K0, K1, S0, S1, T0, T1;
    tf2x32(0u, 42u, 0u, 0u, &K0, &K1);
    tf2x32(0u, 42u, 0u, 1u, &S0, &S1);
    tf2x32(K0, K1, 0u, 1u, &T0, &T1);

    std::vector<uint32_t> k1v((size_t)n), k2v((size_t)n);
    for (int i = 0; i < n; i++) {
        uint32_t a, b;
        tf2x32(S0, S1, 0u, (uint32_t)i, &a, &b); k1v[i] = a ^ b;
        tf2x32(T0, T1, 0u, (uint32_t)i, &a, &b); k2v[i] = a ^ b;
    }
    long q0 = -1, q1 = -1;
    for (int p = 0; p < n; p++) {
        uint32_t v = k2v[p];
        if (q0 < 0 || v < k2v[q0]) { q1 = q0; q0 = p; }
        else if (q1 < 0 || v < k2v[q1]) { q1 = p; }
    }
    std::vector<int> idx((size_t)n);
    for (int i = 0; i < n; i++) idx[i] = i;
    std::stable_sort(idx.begin(), idx.end(),
                     [&](int a, int b) { return k1v[a] < k1v[b]; });
    *pi0 = idx[q0];
    *pi1 = idx[q1];
}

// ---------------- entry ----------------
extern "C" void kernel_launch(void* const* d_in, const int* in_sizes, int n_in,
                              void* d_out, int out_size) {
    const float* x = (const float*)d_in[0];
    const int n = in_sizes[0] / DIMS;

    int i0 = 0, i1 = 1;
    init_indices(n, &i0, &i1);

    const int smem_bytes = 2 * TILE4 * 16;    // 66,560 B dynamic per block
    static bool attr_set = false;
    if (!attr_set) {
        cudaFuncSetAttribute(assign_kernel,
                             cudaFuncAttributeMaxDynamicSharedMemorySize, smem_bytes);
        attr_set = true;
    }

    init_kernel<<<1, DIMS>>>(x, i0, i1);
    xsq_kernel<<<(n + 7) / 8, 256>>>(x, n);
    tot_kernel<<<592, DIMS>>>(x, n);
    for (int t = 0; t < N_ITERS; t++)
        assign_kernel<<<NB, TPB, smem_bytes>>>(x, n, (t < N_ITERS - 1) ? 1 : 0);
    output_kernel<<<1, DIMS>>>((float*)d_out, n);
}